// round 2
// baseline (speedup 1.0000x reference)
#include <cuda_runtime.h>
#include <math.h>

// Problem dims
#define NB 2
#define NS 2048
#define DM 1024
#define DK 64
#define NH 16

// Scratch (allocation-free rule: __device__ globals)
__device__ float g_Q[NB*NH*NS*DK];
__device__ float g_K[NB*NH*NS*DK];
__device__ float g_V[NB*NH*NS*DK];
__device__ float g_ctx[NB*NS*NH*DK];

// ---------------------------------------------------------------------------
// 64x64 tile GEMM core (row-major A [*,lda], row-major B [K,ldb], C [*,ldc])
// 256 threads, thread tile 4x4, K-tile 32.
// ---------------------------------------------------------------------------
__device__ __forceinline__ void gemm64x64_core(
    const float* __restrict__ A, int lda,
    const float* __restrict__ Bm, int ldb,
    float* __restrict__ C, int ldc, int K)
{
    __shared__ __align__(16) float As[64][32];
    __shared__ __align__(16) float Bs[32][64];
    const int tid = threadIdx.x;
    const int tx = tid & 15;   // n direction (x4)
    const int ty = tid >> 4;   // m direction (x4)

    float acc[4][4];
    #pragma unroll
    for (int i = 0; i < 4; i++)
        #pragma unroll
        for (int j = 0; j < 4; j++) acc[i][j] = 0.0f;

    for (int k0 = 0; k0 < K; k0 += 32) {
        // Load A tile: 64 rows x 32 cols = 512 float4
        #pragma unroll
        for (int e = 0; e < 2; e++) {
            int idx = tid + e * 256;
            int r = idx >> 3, vc = idx & 7;
            float4 v = *(const float4*)(A + (size_t)r * lda + k0 + vc * 4);
            *(float4*)(&As[r][vc * 4]) = v;
        }
        // Load B tile: 32 rows x 64 cols = 512 float4
        #pragma unroll
        for (int e = 0; e < 2; e++) {
            int idx = tid + e * 256;
            int r = idx >> 4, vc = idx & 15;
            float4 v = *(const float4*)(Bm + (size_t)(k0 + r) * ldb + vc * 4);
            *(float4*)(&Bs[r][vc * 4]) = v;
        }
        __syncthreads();
        #pragma unroll
        for (int kk = 0; kk < 32; kk++) {
            float4 b = *(const float4*)(&Bs[kk][tx * 4]);
            #pragma unroll
            for (int i = 0; i < 4; i++) {
                float a = As[ty * 4 + i][kk];
                acc[i][0] = fmaf(a, b.x, acc[i][0]);
                acc[i][1] = fmaf(a, b.y, acc[i][1]);
                acc[i][2] = fmaf(a, b.z, acc[i][2]);
                acc[i][3] = fmaf(a, b.w, acc[i][3]);
            }
        }
        __syncthreads();
    }
    #pragma unroll
    for (int i = 0; i < 4; i++) {
        float4 o = make_float4(acc[i][0], acc[i][1], acc[i][2], acc[i][3]);
        *(float4*)(C + (size_t)(ty * 4 + i) * ldc + tx * 4) = o;
    }
}

// ---------------------------------------------------------------------------
// QKV projection: per block z = type*16 + h. Computes out = x_b @ W[h]
// out layout: [B,H,S,DK] so attention rows are contiguous per (b,h).
// ---------------------------------------------------------------------------
__global__ void __launch_bounds__(256) qkv_proj_kernel(
    const float* __restrict__ x,
    const float* __restrict__ Wq,
    const float* __restrict__ Wk,
    const float* __restrict__ Wv)
{
    int m0 = blockIdx.x * 64;            // s-tile
    int b  = blockIdx.y;
    int z  = blockIdx.z;                 // 0..47
    int type = z >> 4;
    int h    = z & 15;

    const float* W;
    float* outb;
    if (type == 0)      { W = Wq; outb = g_Q; }
    else if (type == 1) { W = Wk; outb = g_K; }
    else                { W = Wv; outb = g_V; }
    W += (size_t)h * DM * DK;
    float* out = outb + ((size_t)(b * NH + h) * NS + m0) * DK;
    const float* A = x + (size_t)b * NS * DM + (size_t)m0 * DM;

    gemm64x64_core(A, DM, W, DK, out, DK, DM);
}

// ---------------------------------------------------------------------------
// Flash-style attention. grid (S/128, B*H). 128 threads, 1 thread = 1 q-row.
// K/V tiles of 64 keys in smem; chunked (8) online softmax.
// ---------------------------------------------------------------------------
__global__ void __launch_bounds__(128, 3) attn_kernel()
{
    __shared__ __align__(16) float sK[64 * 64];
    __shared__ __align__(16) float sV[64 * 64];

    const int bh = blockIdx.y;           // b*16 + h
    const int b  = bh >> 4;
    const int h  = bh & 15;
    const int s  = blockIdx.x * 128 + threadIdx.x;

    const float* Qrow  = g_Q + ((size_t)bh * NS + s) * DK;
    const float* Kbase = g_K + (size_t)bh * NS * DK;
    const float* Vbase = g_V + (size_t)bh * NS * DK;

    const float scale = 0.125f;          // 1/sqrt(64)
    float q[DK];
    #pragma unroll
    for (int i = 0; i < 16; i++) {
        float4 v = *(const float4*)(Qrow + i * 4);
        q[4*i+0] = v.x * scale; q[4*i+1] = v.y * scale;
        q[4*i+2] = v.z * scale; q[4*i+3] = v.w * scale;
    }

    float acc[DK];
    #pragma unroll
    for (int i = 0; i < DK; i++) acc[i] = 0.0f;
    float mmax = -INFINITY;
    float l = 0.0f;

    for (int jt = 0; jt < NS; jt += 64) {
        __syncthreads();
        // load 64 keys + 64 values (contiguous 16KB each), coalesced
        const float4* gk = (const float4*)(Kbase + (size_t)jt * DK);
        const float4* gv = (const float4*)(Vbase + (size_t)jt * DK);
        #pragma unroll
        for (int e = 0; e < 8; e++) {
            int idx = threadIdx.x + e * 128;
            ((float4*)sK)[idx] = gk[idx];
            ((float4*)sV)[idx] = gv[idx];
        }
        __syncthreads();

        #pragma unroll 1
        for (int jc = 0; jc < 64; jc += 8) {
            float sc[8];
            #pragma unroll
            for (int j = 0; j < 8; j++) {
                const float* kr = sK + (jc + j) * DK;
                float s0 = 0.f, s1 = 0.f, s2 = 0.f, s3 = 0.f;
                #pragma unroll
                for (int i = 0; i < DK; i += 4) {
                    float4 kv = *(const float4*)(kr + i);
                    s0 = fmaf(q[i + 0], kv.x, s0);
                    s1 = fmaf(q[i + 1], kv.y, s1);
                    s2 = fmaf(q[i + 2], kv.z, s2);
                    s3 = fmaf(q[i + 3], kv.w, s3);
                }
                sc[j] = (s0 + s1) + (s2 + s3);
            }
            float tmax = sc[0];
            #pragma unroll
            for (int j = 1; j < 8; j++) tmax = fmaxf(tmax, sc[j]);
            if (tmax > mmax) {
                float corr = __expf(mmax - tmax);   // first time: exp(-inf)=0
                l *= corr;
                #pragma unroll
                for (int i = 0; i < DK; i++) acc[i] *= corr;
                mmax = tmax;
            }
            #pragma unroll
            for (int j = 0; j < 8; j++) {
                float p = __expf(sc[j] - mmax);
                l += p;
                const float* vr = sV + (jc + j) * DK;
                #pragma unroll
                for (int i = 0; i < DK; i += 4) {
                    float4 vv = *(const float4*)(vr + i);
                    acc[i + 0] = fmaf(p, vv.x, acc[i + 0]);
                    acc[i + 1] = fmaf(p, vv.y, acc[i + 1]);
                    acc[i + 2] = fmaf(p, vv.z, acc[i + 2]);
                    acc[i + 3] = fmaf(p, vv.w, acc[i + 3]);
                }
            }
        }
    }

    float inv = 1.0f / l;
    float* out = g_ctx + ((size_t)(b * NS + s)) * (NH * DK) + h * DK;
    #pragma unroll
    for (int i = 0; i < 16; i++) {
        float4 o = make_float4(acc[4*i+0]*inv, acc[4*i+1]*inv,
                               acc[4*i+2]*inv, acc[4*i+3]*inv);
        *(float4*)(out + 4 * i) = o;
    }
}

// ---------------------------------------------------------------------------
// Output projection: out[4096,1024] = ctx[4096,1024] @ Wo[1024,1024]
// ---------------------------------------------------------------------------
__global__ void __launch_bounds__(256) out_proj_kernel(
    const float* __restrict__ Wo, float* __restrict__ out)
{
    int n0 = blockIdx.x * 64;
    int m0 = blockIdx.y * 64;
    gemm64x64_core(g_ctx + (size_t)m0 * (NH * DK), NH * DK,
                   Wo + n0, DM,
                   out + (size_t)m0 * DM + n0, DM, NH * DK);
}

// ---------------------------------------------------------------------------
extern "C" void kernel_launch(void* const* d_in, const int* in_sizes, int n_in,
                              void* d_out, int out_size)
{
    (void)in_sizes; (void)n_in; (void)out_size;
    // metadata order: x, Wk, Wq, Wv, Wo
    const float* x  = (const float*)d_in[0];
    const float* Wk = (const float*)d_in[1];
    const float* Wq = (const float*)d_in[2];
    const float* Wv = (const float*)d_in[3];
    const float* Wo = (const float*)d_in[4];
    float* out = (float*)d_out;

    qkv_proj_kernel<<<dim3(NS / 64, NB, 48), 256>>>(x, Wq, Wk, Wv);
    attn_kernel<<<dim3(NS / 128, NB * NH), 128>>>();
    out_proj_kernel<<<dim3(DM / 64, (NB * NS) / 64), 256>>>(Wo, out);
}